// round 14
// baseline (speedup 1.0000x reference)
#include <cuda_runtime.h>
#include <cuda_fp16.h>
#include <cstdint>

static constexpr int BATCH = 4;
static constexpr int SEQ   = 2048;
static constexpr int DIM   = 1024;

// Scratch (device globals: allocation-guard safe)
__device__ __half g_x  [BATCH * SEQ * DIM];        // fp16 x
__device__ __half g_w  [3 * DIM * DIM];            // concat Wq|Wk|Wv fp16
__device__ float  g_b  [3 * DIM];                  // concat bq|bk|bv fp32
__device__ __half g_qkv[BATCH * SEQ * 3 * DIM];    // fused Q|K|V rows
__device__ __half g_vt [BATCH * DIM * SEQ];        // V^T: [B][D][S]
__device__ __half g_p  [BATCH * SEQ * SEQ];        // fp16 attention weights

// ---------------------------------------------------------------------------
__device__ __forceinline__ void mma_f16(float (&c)[4],
                                        uint32_t a0, uint32_t a1,
                                        uint32_t a2, uint32_t a3,
                                        uint32_t b0, uint32_t b1) {
    asm volatile(
        "mma.sync.aligned.m16n8k16.row.col.f32.f16.f16.f32 "
        "{%0,%1,%2,%3}, {%4,%5,%6,%7}, {%8,%9}, {%0,%1,%2,%3};\n"
        : "+f"(c[0]), "+f"(c[1]), "+f"(c[2]), "+f"(c[3])
        : "r"(a0), "r"(a1), "r"(a2), "r"(a3), "r"(b0), "r"(b1));
}

__device__ __forceinline__ void ldsm4(uint32_t& r0, uint32_t& r1,
                                      uint32_t& r2, uint32_t& r3, uint32_t addr) {
    asm volatile(
        "ldmatrix.sync.aligned.m8n8.x4.shared.b16 {%0,%1,%2,%3}, [%4];"
        : "=r"(r0), "=r"(r1), "=r"(r2), "=r"(r3) : "r"(addr));
}

#define CPA16(dst, src) \
    asm volatile("cp.async.cg.shared.global [%0], [%1], 16;\n" :: "r"(dst), "l"(src))

// ---------------------------------------------------------------------------
// fp32 -> fp16 conversion passes
// ---------------------------------------------------------------------------
__global__ __launch_bounds__(256)
void cvt_half_kernel(const float* __restrict__ in, __half* __restrict__ out, int n4)
{
    int i = blockIdx.x * 256 + threadIdx.x;
    if (i < n4) {
        float4 v = ((const float4*)in)[i];
        __half2 h01 = __floats2half2_rn(v.x, v.y);
        __half2 h23 = __floats2half2_rn(v.z, v.w);
        uint2 pk;
        pk.x = *(uint32_t*)&h01;
        pk.y = *(uint32_t*)&h23;
        ((uint2*)out)[i] = pk;
    }
}

__global__ __launch_bounds__(256)
void cvt3_kernel(const float* __restrict__ w0, const float* __restrict__ w1,
                 const float* __restrict__ w2, __half* __restrict__ out, int nw4)
{
    int i = blockIdx.x * 256 + threadIdx.x;
    if (i < 3 * nw4) {
        const float* src = (i < nw4) ? w0 : (i < 2 * nw4 ? w1 : w2);
        int j = (i < nw4) ? i : (i < 2 * nw4 ? i - nw4 : i - 2 * nw4);
        float4 v = ((const float4*)src)[j];
        __half2 h01 = __floats2half2_rn(v.x, v.y);
        __half2 h23 = __floats2half2_rn(v.z, v.w);
        uint2 pk;
        pk.x = *(uint32_t*)&h01;
        pk.y = *(uint32_t*)&h23;
        ((uint2*)out)[i] = pk;
    }
}

__global__ __launch_bounds__(256)
void bias3_kernel(const float* __restrict__ b0, const float* __restrict__ b1,
                  const float* __restrict__ b2, float* __restrict__ out)
{
    int i = blockIdx.x * 256 + threadIdx.x;
    if (i < DIM)           out[i] = b0[i];
    else if (i < 2 * DIM)  out[i] = b1[i - DIM];
    else if (i < 3 * DIM)  out[i] = b2[i - 2 * DIM];
}

// ---------------------------------------------------------------------------
// FP16 tensor-core GEMM (fp32 accum):  C = alpha * (A @ B^T) + bias
//   A [M x K] lda, B [N x K] ldb, row-major fp16, explicit leading dims.
// 64x128 block tile, BK=32, 128 threads (4 warps, 64x32 warp tiles),
// 3-stage cp.async ring with ONE __syncthreads per K-tile, ldmatrix
// fragment loads from XOR-swizzled 64B-row tiles, mma.m16n8k16,
// 4 CTAs/SM (independent barrier domains for latency overlap).
//   HALF_OUT: store C fp16 (operand reuse); else fp32.
// ---------------------------------------------------------------------------
template <bool HALF_OUT>
__global__ __launch_bounds__(128, 4)
void gemm_h(const __half* __restrict__ A, const __half* __restrict__ B,
            const float* __restrict__ bias, void* __restrict__ C,
            int N, int K, int lda, int ldb, int ldc, float alpha,
            long sA, long sB, long sC)
{
    constexpr int BK = 32;
    constexpr int A_H   = 64  * 32;            // A tile halves (4 KB)
    constexpr int B_H   = 128 * 32;            // B tile halves (8 KB)
    constexpr int STG_H = A_H + B_H;           // stage halves (12 KB)

    extern __shared__ __half smh[];
    uint32_t sbase;
    asm("{ .reg .u64 t; cvta.to.shared.u64 t, %1; cvt.u32.u64 %0, t; }"
        : "=r"(sbase) : "l"(smh));

    const __half* Ab = A + (long)blockIdx.z * sA;
    const __half* Bb = B + (long)blockIdx.z * sB;

    const int n0   = blockIdx.x * 128;
    const int m0   = blockIdx.y * 64;
    const int tid  = threadIdx.x;
    const int warp = tid >> 5;
    const int lane = tid & 31;
    const int g    = lane >> 2;
    const int tg   = lane & 3;
    const int wn   = warp * 32;                // 4 warps across N

    // Per-lane LDSM addressing
    const int lrow = ((lane >> 3) & 1) * 8 + (lane & 7);   // 0..15
    const uint32_t hi = lane >> 4;                          // 0/1

    uint32_t offA[4], swA[4];
    #pragma unroll
    for (int mi = 0; mi < 4; ++mi) {
        int r = mi * 16 + lrow;                // A rows 0..63 (shared by warps)
        offA[mi] = (uint32_t)r * 64u;
        swA[mi]  = ((uint32_t)r >> 1) & 3u;
    }
    uint32_t offB[2], swB[2];
    #pragma unroll
    for (int nj = 0; nj < 2; ++nj) {
        int r = wn + nj * 16 + lrow;           // B rows 0..127
        offB[nj] = (uint32_t)r * 64u;
        swB[nj]  = ((uint32_t)r >> 1) & 3u;
    }

    float acc[4][4][4];
    #pragma unroll
    for (int i = 0; i < 4; ++i)
        #pragma unroll
        for (int j = 0; j < 4; ++j)
            #pragma unroll
            for (int r = 0; r < 4; ++r) acc[i][j][r] = 0.0f;

    // Loader (128 threads): A 64 rows x 2 threads/row x 2 chunks;
    //                       B 128 rows x 1 thread/row x 4 chunks.
    auto load_tile = [&](int kt, int s) {
        const int k0 = kt * BK;
        {
            const int cr = tid >> 1;
            const int cp = (tid & 1) * 2;
            const uint32_t sw = ((uint32_t)cr >> 1) & 3u;
            const uint32_t abase = sbase + (uint32_t)(s * STG_H) * 2u
                                         + (uint32_t)cr * 64u;
            const __half* asrc = Ab + (long)(m0 + cr) * lda + k0 + cp * 8;
            CPA16(abase + ((((uint32_t)cp    ) ^ sw) << 4), asrc);
            CPA16(abase + ((((uint32_t)cp + 1) ^ sw) << 4), asrc + 8);
        }
        {
            const int cr = tid;                // 0..127
            const uint32_t sw = ((uint32_t)cr >> 1) & 3u;
            const uint32_t bbase = sbase + (uint32_t)(s * STG_H + A_H) * 2u
                                         + (uint32_t)cr * 64u;
            const __half* bsrc = Bb + (long)(n0 + cr) * ldb + k0;
            #pragma unroll
            for (int c = 0; c < 4; ++c)
                CPA16(bbase + ((((uint32_t)c) ^ sw) << 4), bsrc + c * 8);
        }
        asm volatile("cp.async.commit_group;\n");
    };

    const int ntiles = K / BK;
    load_tile(0, 0);
    load_tile(1, 1);

    for (int kt = 0; kt < ntiles; ++kt) {
        const int s = kt % 3;
        if (kt + 1 < ntiles) asm volatile("cp.async.wait_group 1;\n");
        else                 asm volatile("cp.async.wait_group 0;\n");
        __syncthreads();
        // Stage (kt+2)%3 was last read in iteration kt-1; the barrier above
        // guarantees all warps finished that compute.
        if (kt + 2 < ntiles) load_tile(kt + 2, (kt + 2) % 3);

        const uint32_t Ab32 = sbase + (uint32_t)(s * STG_H) * 2u;
        const uint32_t Bb32 = Ab32 + (uint32_t)A_H * 2u;

        #pragma unroll
        for (int kk = 0; kk < 2; ++kk) {       // 2 x K=16 per BK=32
            const uint32_t c0 = (uint32_t)(kk * 2) + hi;
            uint32_t af[4][4], bf[2][4];
            #pragma unroll
            for (int mi = 0; mi < 4; ++mi)
                ldsm4(af[mi][0], af[mi][1], af[mi][2], af[mi][3],
                      Ab32 + offA[mi] + ((c0 ^ swA[mi]) << 4));
            #pragma unroll
            for (int nj = 0; nj < 2; ++nj)
                ldsm4(bf[nj][0], bf[nj][1], bf[nj][2], bf[nj][3],
                      Bb32 + offB[nj] + ((c0 ^ swB[nj]) << 4));
            #pragma unroll
            for (int mi = 0; mi < 4; ++mi)
                #pragma unroll
                for (int ni = 0; ni < 4; ++ni) {
                    const int nj = ni >> 1, lo = ni & 1;
                    mma_f16(acc[mi][ni], af[mi][0], af[mi][1], af[mi][2],
                            af[mi][3], bf[nj][lo], bf[nj][2 + lo]);
                }
        }
    }

    // Epilogue
    #pragma unroll
    for (int mi = 0; mi < 4; ++mi) {
        const int row = m0 + mi * 16 + g;
        #pragma unroll
        for (int ni = 0; ni < 4; ++ni) {
            const int col = n0 + wn + ni * 8 + tg * 2;
            float v0 = acc[mi][ni][0] * alpha, v1 = acc[mi][ni][1] * alpha;
            float v2 = acc[mi][ni][2] * alpha, v3 = acc[mi][ni][3] * alpha;
            if (bias) {
                float2 b = *(const float2*)&bias[col];
                v0 += b.x; v1 += b.y; v2 += b.x; v3 += b.y;
            }
            if (HALF_OUT) {
                __half* Cb = (__half*)C + (long)blockIdx.z * sC;
                __half2 h0 = __floats2half2_rn(v0, v1);
                __half2 h1 = __floats2half2_rn(v2, v3);
                *(__half2*)&Cb[(long)row * ldc + col]       = h0;
                *(__half2*)&Cb[(long)(row + 8) * ldc + col] = h1;
            } else {
                float* Cb = (float*)C + (long)blockIdx.z * sC;
                *(float2*)&Cb[(long)row * ldc + col]       = make_float2(v0, v1);
                *(float2*)&Cb[(long)(row + 8) * ldc + col] = make_float2(v2, v3);
            }
        }
    }
}

// ---------------------------------------------------------------------------
// V transpose (fp16): V rows inside qkv [B*S x 3*DIM] -> [B][D][S]
// ---------------------------------------------------------------------------
__global__ __launch_bounds__(256)
void transpose_h(const __half* __restrict__ qkv, __half* __restrict__ out)
{
    __shared__ __half t[32][34];
    const __half* ib = qkv + (long)blockIdx.z * SEQ * (3 * DIM) + 2 * DIM;
    __half*       ob = out + (long)blockIdx.z * DIM * SEQ;
    const int d0 = blockIdx.x * 32;
    const int s0 = blockIdx.y * 32;
    const int tx = threadIdx.x;
    const int ty = threadIdx.y;
    #pragma unroll
    for (int j = 0; j < 32; j += 8)
        t[ty + j][tx] = ib[(long)(s0 + ty + j) * (3 * DIM) + d0 + tx];
    __syncthreads();
    #pragma unroll
    for (int j = 0; j < 32; j += 8)
        ob[(long)(d0 + ty + j) * SEQ + s0 + tx] = t[tx][ty + j];
}

// ---------------------------------------------------------------------------
// Row softmax, float4-vectorized: thread t owns elements [8t, 8t+8).
// Exact fp32 -> data (in place); fp16 copy -> ph.
// ---------------------------------------------------------------------------
__global__ __launch_bounds__(256)
void softmax_kernel(float* __restrict__ data, __half* __restrict__ ph)
{
    const long roff = (long)blockIdx.x * SEQ;
    float4* r4 = (float4*)(data + roff);
    uint4*  h4 = (uint4*)(ph + roff);
    __shared__ float red[8];

    const int tid  = threadIdx.x;
    const int lane = tid & 31;
    const int warp = tid >> 5;

    float4 va = r4[2 * tid];
    float4 vb = r4[2 * tid + 1];

    float lmax = fmaxf(fmaxf(fmaxf(va.x, va.y), fmaxf(va.z, va.w)),
                       fmaxf(fmaxf(vb.x, vb.y), fmaxf(vb.z, vb.w)));
    #pragma unroll
    for (int o = 16; o > 0; o >>= 1)
        lmax = fmaxf(lmax, __shfl_xor_sync(0xFFFFFFFFu, lmax, o));
    if (lane == 0) red[warp] = lmax;
    __syncthreads();
    float rmax = red[0];
    #pragma unroll
    for (int w = 1; w < 8; ++w) rmax = fmaxf(rmax, red[w]);
    __syncthreads();

    va.x = __expf(va.x - rmax); va.y = __expf(va.y - rmax);
    va.z = __expf(va.z - rmax); va.w = __expf(va.w - rmax);
    vb.x = __expf(vb.x - rmax); vb.y = __expf(vb.y - rmax);
    vb.z = __expf(vb.z - rmax); vb.w = __expf(vb.w - rmax);

    float lsum = (va.x + va.y) + (va.z + va.w) + (vb.x + vb.y) + (vb.z + vb.w);
    #pragma unroll
    for (int o = 16; o > 0; o >>= 1)
        lsum += __shfl_xor_sync(0xFFFFFFFFu, lsum, o);
    if (lane == 0) red[warp] = lsum;
    __syncthreads();
    float rsum = 0.0f;
    #pragma unroll
    for (int w = 0; w < 8; ++w) rsum += red[w];

    const float inv = 1.0f / rsum;
    va.x *= inv; va.y *= inv; va.z *= inv; va.w *= inv;
    vb.x *= inv; vb.y *= inv; vb.z *= inv; vb.w *= inv;

    r4[2 * tid]     = va;
    r4[2 * tid + 1] = vb;

    __half2 p0 = __floats2half2_rn(va.x, va.y);
    __half2 p1 = __floats2half2_rn(va.z, va.w);
    __half2 p2 = __floats2half2_rn(vb.x, vb.y);
    __half2 p3 = __floats2half2_rn(vb.z, vb.w);
    uint4 pk;
    pk.x = *(uint32_t*)&p0; pk.y = *(uint32_t*)&p1;
    pk.z = *(uint32_t*)&p2; pk.w = *(uint32_t*)&p3;
    h4[tid] = pk;
}

// ---------------------------------------------------------------------------
// Launch: cvt -> fused QKV proj -> V^T -> scores -> softmax -> AV
// Output layout: [weighted_sum B*S*D | attention_weights B*S*S]
// ---------------------------------------------------------------------------
extern "C" void kernel_launch(void* const* d_in, const int* in_sizes, int n_in,
                              void* d_out, int out_size)
{
    const float* x  = (const float*)d_in[0];
    const float* Wq = (const float*)d_in[1];
    const float* bq = (const float*)d_in[2];
    const float* Wk = (const float*)d_in[3];
    const float* bk = (const float*)d_in[4];
    const float* Wv = (const float*)d_in[5];
    const float* bv = (const float*)d_in[6];

    float* out_ws = (float*)d_out;
    float* out_aw = (float*)d_out + (long)BATCH * SEQ * DIM;

    __half *xh, *w, *qkv, *vt, *p;
    float* b;
    cudaGetSymbolAddress((void**)&xh,  g_x);
    cudaGetSymbolAddress((void**)&w,   g_w);
    cudaGetSymbolAddress((void**)&b,   g_b);
    cudaGetSymbolAddress((void**)&qkv, g_qkv);
    cudaGetSymbolAddress((void**)&vt,  g_vt);
    cudaGetSymbolAddress((void**)&p,   g_p);

    // smem: 3 stages x 12288 B = 36864 B per CTA (4 CTAs/SM = 144 KB)
    const int smem_sz = 3 * (64 * 32 + 128 * 32) * 2;
    cudaFuncSetAttribute(gemm_h<true >, cudaFuncAttributeMaxDynamicSharedMemorySize, smem_sz);
    cudaFuncSetAttribute(gemm_h<false>, cudaFuncAttributeMaxDynamicSharedMemorySize, smem_sz);

    const dim3 blk(128);
    const dim3 blk256(256);

    // 0) convert inputs to fp16 (x; Wq|Wk|Wv concat; bias concat)
    {
        const int nx = BATCH * SEQ * DIM / 4;
        const int nw = DIM * DIM / 4;
        cvt_half_kernel<<<(nx + 255) / 256, blk256>>>(x, xh, nx);
        cvt3_kernel<<<(3 * nw + 255) / 256, blk256>>>(Wq, Wk, Wv, w, nw);
        bias3_kernel<<<(3 * DIM + 255) / 256, blk256>>>(bq, bk, bv, b);
    }

    // 1) Fused QKV projection: [8192, 3072] = xh @ W^T + b, fp16 out
    {
        dim3 grid((3 * DIM) / 128, (BATCH * SEQ) / 64, 1);
        gemm_h<true><<<grid, blk, smem_sz>>>(xh, w, b, qkv,
                                             3 * DIM, DIM,
                                             DIM, DIM, 3 * DIM, 1.0f, 0, 0, 0);
    }

    // 2) V^T: [S,D] (stride 3*DIM inside qkv) -> [D,S] fp16
    {
        dim3 tgrid(DIM / 32, SEQ / 32, BATCH);
        transpose_h<<<tgrid, dim3(32, 8)>>>(qkv, vt);
    }

    // 3) scores = (Q @ K^T) / 32, fp32 into attention-weights region
    {
        dim3 grid(SEQ / 128, SEQ / 64, BATCH);
        gemm_h<false><<<grid, blk, smem_sz>>>(qkv, qkv + DIM, nullptr, out_aw,
                                              SEQ, DIM,
                                              3 * DIM, 3 * DIM, SEQ, 0.03125f,
                                              (long)SEQ * 3 * DIM,
                                              (long)SEQ * 3 * DIM,
                                              (long)SEQ * SEQ);
    }

    // 4) softmax: exact fp32 -> out_aw, fp16 -> p
    softmax_kernel<<<BATCH * SEQ, blk256>>>(out_aw, p);

    // 5) weighted_sum = P @ Vt^T  (Vt: [D,S] = B[N=D,K=S]), fp32 out
    {
        dim3 grid(DIM / 128, SEQ / 64, BATCH);
        gemm_h<false><<<grid, blk, smem_sz>>>(p, vt, nullptr, out_ws,
                                              DIM, SEQ,
                                              SEQ, SEQ, DIM, 1.0f,
                                              (long)SEQ * SEQ,
                                              (long)DIM * SEQ,
                                              (long)SEQ * DIM);
    }
}

// round 15
// speedup vs baseline: 1.2503x; 1.2503x over previous
#include <cuda_runtime.h>
#include <cuda_fp16.h>
#include <cstdint>

static constexpr int BATCH = 4;
static constexpr int SEQ   = 2048;
static constexpr int DIM   = 1024;

// Scratch (device globals: allocation-guard safe)
__device__ __half g_x  [BATCH * SEQ * DIM];        // fp16 x
__device__ __half g_w  [3 * DIM * DIM];            // concat Wq|Wk|Wv fp16
__device__ float  g_b  [3 * DIM];                  // concat bq|bk|bv fp32
__device__ __half g_qkv[BATCH * SEQ * 3 * DIM];    // fused Q|K|V rows
__device__ __half g_vt [BATCH * DIM * SEQ];        // V^T: [B][D][S]
__device__ __half g_p  [BATCH * SEQ * SEQ];        // fp16 attention weights

// ---------------------------------------------------------------------------
__device__ __forceinline__ void mma_f16(float (&c)[4],
                                        uint32_t a0, uint32_t a1,
                                        uint32_t a2, uint32_t a3,
                                        uint32_t b0, uint32_t b1) {
    asm volatile(
        "mma.sync.aligned.m16n8k16.row.col.f32.f16.f16.f32 "
        "{%0,%1,%2,%3}, {%4,%5,%6,%7}, {%8,%9}, {%0,%1,%2,%3};\n"
        : "+f"(c[0]), "+f"(c[1]), "+f"(c[2]), "+f"(c[3])
        : "r"(a0), "r"(a1), "r"(a2), "r"(a3), "r"(b0), "r"(b1));
}

__device__ __forceinline__ void ldsm4(uint32_t& r0, uint32_t& r1,
                                      uint32_t& r2, uint32_t& r3, uint32_t addr) {
    asm volatile(
        "ldmatrix.sync.aligned.m8n8.x4.shared.b16 {%0,%1,%2,%3}, [%4];"
        : "=r"(r0), "=r"(r1), "=r"(r2), "=r"(r3) : "r"(addr));
}

#define CPA16(dst, src) \
    asm volatile("cp.async.cg.shared.global [%0], [%1], 16;\n" :: "r"(dst), "l"(src))

// ---------------------------------------------------------------------------
// fp32 -> fp16 conversion passes
// ---------------------------------------------------------------------------
__global__ __launch_bounds__(256)
void cvt_half_kernel(const float* __restrict__ in, __half* __restrict__ out, int n4)
{
    int i = blockIdx.x * 256 + threadIdx.x;
    if (i < n4) {
        float4 v = ((const float4*)in)[i];
        __half2 h01 = __floats2half2_rn(v.x, v.y);
        __half2 h23 = __floats2half2_rn(v.z, v.w);
        uint2 pk;
        pk.x = *(uint32_t*)&h01;
        pk.y = *(uint32_t*)&h23;
        ((uint2*)out)[i] = pk;
    }
}

__global__ __launch_bounds__(256)
void cvt3_kernel(const float* __restrict__ w0, const float* __restrict__ w1,
                 const float* __restrict__ w2, __half* __restrict__ out, int nw4)
{
    int i = blockIdx.x * 256 + threadIdx.x;
    if (i < 3 * nw4) {
        const float* src = (i < nw4) ? w0 : (i < 2 * nw4 ? w1 : w2);
        int j = (i < nw4) ? i : (i < 2 * nw4 ? i - nw4 : i - 2 * nw4);
        float4 v = ((const float4*)src)[j];
        __half2 h01 = __floats2half2_rn(v.x, v.y);
        __half2 h23 = __floats2half2_rn(v.z, v.w);
        uint2 pk;
        pk.x = *(uint32_t*)&h01;
        pk.y = *(uint32_t*)&h23;
        ((uint2*)out)[i] = pk;
    }
}

__global__ __launch_bounds__(256)
void bias3_kernel(const float* __restrict__ b0, const float* __restrict__ b1,
                  const float* __restrict__ b2, float* __restrict__ out)
{
    int i = blockIdx.x * 256 + threadIdx.x;
    if (i < DIM)           out[i] = b0[i];
    else if (i < 2 * DIM)  out[i] = b1[i - DIM];
    else if (i < 3 * DIM)  out[i] = b2[i - 2 * DIM];
}

// ---------------------------------------------------------------------------
// FP16 tensor-core GEMM (fp32 accum):  C = alpha * (A @ B^T) + bias
//   A [M x K] lda, B [N x K] ldb, row-major fp16, explicit leading dims.
// 128x256 block tile, BK=32, 512 threads (16 warps, 64x32 warp tiles),
// 3-stage cp.async ring with ONE __syncthreads per K-tile, ldmatrix
// fragment loads from XOR-swizzled 64B-row tiles, mma.m16n8k16, 1 CTA/SM
// (same 16 warps/SM as 2x256 config, 25% less operand traffic per MAC).
//   HALF_OUT: store C fp16 (operand reuse); else fp32.
// ---------------------------------------------------------------------------
template <bool HALF_OUT>
__global__ __launch_bounds__(512, 1)
void gemm_h(const __half* __restrict__ A, const __half* __restrict__ B,
            const float* __restrict__ bias, void* __restrict__ C,
            int N, int K, int lda, int ldb, int ldc, float alpha,
            long sA, long sB, long sC)
{
    constexpr int BK  = 32;
    constexpr int A_H   = 128 * 32;            // A tile halves (8 KB)
    constexpr int B_H   = 256 * 32;            // B tile halves (16 KB)
    constexpr int STG_H = A_H + B_H;           // stage halves (24 KB)

    extern __shared__ __half smh[];
    uint32_t sbase;
    asm("{ .reg .u64 t; cvta.to.shared.u64 t, %1; cvt.u32.u64 %0, t; }"
        : "=r"(sbase) : "l"(smh));

    const __half* Ab = A + (long)blockIdx.z * sA;
    const __half* Bb = B + (long)blockIdx.z * sB;

    const int n0   = blockIdx.x * 256;
    const int m0   = blockIdx.y * 128;
    const int tid  = threadIdx.x;
    const int warp = tid >> 5;
    const int lane = tid & 31;
    const int g    = lane >> 2;
    const int tg   = lane & 3;
    const int wm   = (warp & 1) * 64;          // 2 warps across M
    const int wn   = (warp >> 1) * 32;         // 8 warps across N

    // Per-lane LDSM addressing
    const int lrow = ((lane >> 3) & 1) * 8 + (lane & 7);   // 0..15
    const uint32_t hi = lane >> 4;                          // 0/1

    uint32_t offA[4], swA[4];
    #pragma unroll
    for (int mi = 0; mi < 4; ++mi) {
        int r = wm + mi * 16 + lrow;
        offA[mi] = (uint32_t)r * 64u;
        swA[mi]  = ((uint32_t)r >> 1) & 3u;
    }
    uint32_t offB[2], swB[2];
    #pragma unroll
    for (int nj = 0; nj < 2; ++nj) {
        int r = wn + nj * 16 + lrow;
        offB[nj] = (uint32_t)r * 64u;
        swB[nj]  = ((uint32_t)r >> 1) & 3u;
    }

    float acc[4][4][4];
    #pragma unroll
    for (int i = 0; i < 4; ++i)
        #pragma unroll
        for (int j = 0; j < 4; ++j)
            #pragma unroll
            for (int r = 0; r < 4; ++r) acc[i][j][r] = 0.0f;

    // Loader (512 threads): A 128 rows x 4 chunks -> 1 chunk/thread;
    //                       B 256 rows x 4 chunks -> 2 chunks/thread.
    auto load_tile = [&](int kt, int s) {
        const int k0 = kt * BK;
        {
            const int cr = tid >> 2;           // 0..127
            const int cp = tid & 3;            // chunk 0..3
            const uint32_t sw = ((uint32_t)cr >> 1) & 3u;
            const uint32_t abase = sbase + (uint32_t)(s * STG_H) * 2u
                                         + (uint32_t)cr * 64u;
            CPA16(abase + ((((uint32_t)cp) ^ sw) << 4),
                  Ab + (long)(m0 + cr) * lda + k0 + cp * 8);
        }
        {
            const int cr = tid >> 1;           // 0..255
            const int cp = (tid & 1) * 2;      // chunks cp, cp+1
            const uint32_t sw = ((uint32_t)cr >> 1) & 3u;
            const uint32_t bbase = sbase + (uint32_t)(s * STG_H + A_H) * 2u
                                         + (uint32_t)cr * 64u;
            const __half* bsrc = Bb + (long)(n0 + cr) * ldb + k0 + cp * 8;
            CPA16(bbase + ((((uint32_t)cp    ) ^ sw) << 4), bsrc);
            CPA16(bbase + ((((uint32_t)cp + 1) ^ sw) << 4), bsrc + 8);
        }
        asm volatile("cp.async.commit_group;\n");
    };

    const int ntiles = K / BK;
    load_tile(0, 0);
    load_tile(1, 1);

    for (int kt = 0; kt < ntiles; ++kt) {
        const int s = kt % 3;
        if (kt + 1 < ntiles) asm volatile("cp.async.wait_group 1;\n");
        else                 asm volatile("cp.async.wait_group 0;\n");
        __syncthreads();
        // Stage (kt+2)%3 was last read in iteration kt-1; the barrier above
        // guarantees all warps finished that compute.
        if (kt + 2 < ntiles) load_tile(kt + 2, (kt + 2) % 3);

        const uint32_t Ab32 = sbase + (uint32_t)(s * STG_H) * 2u;
        const uint32_t Bb32 = Ab32 + (uint32_t)A_H * 2u;

        #pragma unroll
        for (int kk = 0; kk < 2; ++kk) {       // 2 x K=16 per BK=32
            const uint32_t c0 = (uint32_t)(kk * 2) + hi;
            uint32_t af[4][4], bf[2][4];
            #pragma unroll
            for (int mi = 0; mi < 4; ++mi)
                ldsm4(af[mi][0], af[mi][1], af[mi][2], af[mi][3],
                      Ab32 + offA[mi] + ((c0 ^ swA[mi]) << 4));
            #pragma unroll
            for (int nj = 0; nj < 2; ++nj)
                ldsm4(bf[nj][0], bf[nj][1], bf[nj][2], bf[nj][3],
                      Bb32 + offB[nj] + ((c0 ^ swB[nj]) << 4));
            #pragma unroll
            for (int mi = 0; mi < 4; ++mi)
                #pragma unroll
                for (int ni = 0; ni < 4; ++ni) {
                    const int nj = ni >> 1, lo = ni & 1;
                    mma_f16(acc[mi][ni], af[mi][0], af[mi][1], af[mi][2],
                            af[mi][3], bf[nj][lo], bf[nj][2 + lo]);
                }
        }
    }

    // Epilogue
    #pragma unroll
    for (int mi = 0; mi < 4; ++mi) {
        const int row = m0 + wm + mi * 16 + g;
        #pragma unroll
        for (int ni = 0; ni < 4; ++ni) {
            const int col = n0 + wn + ni * 8 + tg * 2;
            float v0 = acc[mi][ni][0] * alpha, v1 = acc[mi][ni][1] * alpha;
            float v2 = acc[mi][ni][2] * alpha, v3 = acc[mi][ni][3] * alpha;
            if (bias) {
                float2 b = *(const float2*)&bias[col];
                v0 += b.x; v1 += b.y; v2 += b.x; v3 += b.y;
            }
            if (HALF_OUT) {
                __half* Cb = (__half*)C + (long)blockIdx.z * sC;
                __half2 h0 = __floats2half2_rn(v0, v1);
                __half2 h1 = __floats2half2_rn(v2, v3);
                *(__half2*)&Cb[(long)row * ldc + col]       = h0;
                *(__half2*)&Cb[(long)(row + 8) * ldc + col] = h1;
            } else {
                float* Cb = (float*)C + (long)blockIdx.z * sC;
                *(float2*)&Cb[(long)row * ldc + col]       = make_float2(v0, v1);
                *(float2*)&Cb[(long)(row + 8) * ldc + col] = make_float2(v2, v3);
            }
        }
    }
}

// ---------------------------------------------------------------------------
// V transpose (fp16): V rows inside qkv [B*S x 3*DIM] -> [B][D][S]
// ---------------------------------------------------------------------------
__global__ __launch_bounds__(256)
void transpose_h(const __half* __restrict__ qkv, __half* __restrict__ out)
{
    __shared__ __half t[32][34];
    const __half* ib = qkv + (long)blockIdx.z * SEQ * (3 * DIM) + 2 * DIM;
    __half*       ob = out + (long)blockIdx.z * DIM * SEQ;
    const int d0 = blockIdx.x * 32;
    const int s0 = blockIdx.y * 32;
    const int tx = threadIdx.x;
    const int ty = threadIdx.y;
    #pragma unroll
    for (int j = 0; j < 32; j += 8)
        t[ty + j][tx] = ib[(long)(s0 + ty + j) * (3 * DIM) + d0 + tx];
    __syncthreads();
    #pragma unroll
    for (int j = 0; j < 32; j += 8)
        ob[(long)(d0 + ty + j) * SEQ + s0 + tx] = t[tx][ty + j];
}

// ---------------------------------------------------------------------------
// Row softmax, float4-vectorized: thread t owns elements [8t, 8t+8).
// Exact fp32 -> data (in place); fp16 copy -> ph.
// ---------------------------------------------------------------------------
__global__ __launch_bounds__(256)
void softmax_kernel(float* __restrict__ data, __half* __restrict__ ph)
{
    const long roff = (long)blockIdx.x * SEQ;
    float4* r4 = (float4*)(data + roff);
    uint4*  h4 = (uint4*)(ph + roff);
    __shared__ float red[8];

    const int tid  = threadIdx.x;
    const int lane = tid & 31;
    const int warp = tid >> 5;

    float4 va = r4[2 * tid];
    float4 vb = r4[2 * tid + 1];

    float lmax = fmaxf(fmaxf(fmaxf(va.x, va.y), fmaxf(va.z, va.w)),
                       fmaxf(fmaxf(vb.x, vb.y), fmaxf(vb.z, vb.w)));
    #pragma unroll
    for (int o = 16; o > 0; o >>= 1)
        lmax = fmaxf(lmax, __shfl_xor_sync(0xFFFFFFFFu, lmax, o));
    if (lane == 0) red[warp] = lmax;
    __syncthreads();
    float rmax = red[0];
    #pragma unroll
    for (int w = 1; w < 8; ++w) rmax = fmaxf(rmax, red[w]);
    __syncthreads();

    va.x = __expf(va.x - rmax); va.y = __expf(va.y - rmax);
    va.z = __expf(va.z - rmax); va.w = __expf(va.w - rmax);
    vb.x = __expf(vb.x - rmax); vb.y = __expf(vb.y - rmax);
    vb.z = __expf(vb.z - rmax); vb.w = __expf(vb.w - rmax);

    float lsum = (va.x + va.y) + (va.z + va.w) + (vb.x + vb.y) + (vb.z + vb.w);
    #pragma unroll
    for (int o = 16; o > 0; o >>= 1)
        lsum += __shfl_xor_sync(0xFFFFFFFFu, lsum, o);
    if (lane == 0) red[warp] = lsum;
    __syncthreads();
    float rsum = 0.0f;
    #pragma unroll
    for (int w = 0; w < 8; ++w) rsum += red[w];

    const float inv = 1.0f / rsum;
    va.x *= inv; va.y *= inv; va.z *= inv; va.w *= inv;
    vb.x *= inv; vb.y *= inv; vb.z *= inv; vb.w *= inv;

    r4[2 * tid]     = va;
    r4[2 * tid + 1] = vb;

    __half2 p0 = __floats2half2_rn(va.x, va.y);
    __half2 p1 = __floats2half2_rn(va.z, va.w);
    __half2 p2 = __floats2half2_rn(vb.x, vb.y);
    __half2 p3 = __floats2half2_rn(vb.z, vb.w);
    uint4 pk;
    pk.x = *(uint32_t*)&p0; pk.y = *(uint32_t*)&p1;
    pk.z = *(uint32_t*)&p2; pk.w = *(uint32_t*)&p3;
    h4[tid] = pk;
}

// ---------------------------------------------------------------------------
// Launch: cvt -> fused QKV proj -> V^T -> scores -> softmax -> AV
// Output layout: [weighted_sum B*S*D | attention_weights B*S*S]
// ---------------------------------------------------------------------------
extern "C" void kernel_launch(void* const* d_in, const int* in_sizes, int n_in,
                              void* d_out, int out_size)
{
    const float* x  = (const float*)d_in[0];
    const float* Wq = (const float*)d_in[1];
    const float* bq = (const float*)d_in[2];
    const float* Wk = (const float*)d_in[3];
    const float* bk = (const float*)d_in[4];
    const float* Wv = (const float*)d_in[5];
    const float* bv = (const float*)d_in[6];

    float* out_ws = (float*)d_out;
    float* out_aw = (float*)d_out + (long)BATCH * SEQ * DIM;

    __half *xh, *w, *qkv, *vt, *p;
    float* b;
    cudaGetSymbolAddress((void**)&xh,  g_x);
    cudaGetSymbolAddress((void**)&w,   g_w);
    cudaGetSymbolAddress((void**)&b,   g_b);
    cudaGetSymbolAddress((void**)&qkv, g_qkv);
    cudaGetSymbolAddress((void**)&vt,  g_vt);
    cudaGetSymbolAddress((void**)&p,   g_p);

    // smem: 3 stages x 24576 B = 73728 B per CTA (1 CTA/SM)
    const int smem_sz = 3 * (128 * 32 + 256 * 32) * 2;
    cudaFuncSetAttribute(gemm_h<true >, cudaFuncAttributeMaxDynamicSharedMemorySize, smem_sz);
    cudaFuncSetAttribute(gemm_h<false>, cudaFuncAttributeMaxDynamicSharedMemorySize, smem_sz);

    const dim3 blk(512);
    const dim3 blk256(256);

    // 0) convert inputs to fp16 (x; Wq|Wk|Wv concat; bias concat)
    {
        const int nx = BATCH * SEQ * DIM / 4;
        const int nw = DIM * DIM / 4;
        cvt_half_kernel<<<(nx + 255) / 256, blk256>>>(x, xh, nx);
        cvt3_kernel<<<(3 * nw + 255) / 256, blk256>>>(Wq, Wk, Wv, w, nw);
        bias3_kernel<<<(3 * DIM + 255) / 256, blk256>>>(bq, bk, bv, b);
    }

    // 1) Fused QKV projection: [8192, 3072] = xh @ W^T + b, fp16 out
    {
        dim3 grid((3 * DIM) / 256, (BATCH * SEQ) / 128, 1);
        gemm_h<true><<<grid, blk, smem_sz>>>(xh, w, b, qkv,
                                             3 * DIM, DIM,
                                             DIM, DIM, 3 * DIM, 1.0f, 0, 0, 0);
    }

    // 2) V^T: [S,D] (stride 3*DIM inside qkv) -> [D,S] fp16
    {
        dim3 tgrid(DIM / 32, SEQ / 32, BATCH);
        transpose_h<<<tgrid, dim3(32, 8)>>>(qkv, vt);
    }

    // 3) scores = (Q @ K^T) / 32, fp32 into attention-weights region
    {
        dim3 grid(SEQ / 256, SEQ / 128, BATCH);
        gemm_h<false><<<grid, blk, smem_sz>>>(qkv, qkv + DIM, nullptr, out_aw,
                                              SEQ, DIM,
                                              3 * DIM, 3 * DIM, SEQ, 0.03125f,
                                              (long)SEQ * 3 * DIM,
                                              (long)SEQ * 3 * DIM,
                                              (long)SEQ * SEQ);
    }

    // 4) softmax: exact fp32 -> out_aw, fp16 -> p
    softmax_kernel<<<BATCH * SEQ, blk256>>>(out_aw, p);

    // 5) weighted_sum = P @ Vt^T  (Vt: [D,S] = B[N=D,K=S]), fp32 out
    {
        dim3 grid(DIM / 256, SEQ / 128, BATCH);
        gemm_h<false><<<grid, blk, smem_sz>>>(p, vt, nullptr, out_ws,
                                              DIM, SEQ,
                                              SEQ, SEQ, DIM, 1.0f,
                                              (long)SEQ * SEQ,
                                              (long)DIM * SEQ,
                                              (long)SEQ * DIM);
    }
}

// round 16
// speedup vs baseline: 1.3207x; 1.0563x over previous
#include <cuda_runtime.h>
#include <cuda_fp16.h>
#include <cstdint>

static constexpr int BATCH = 4;
static constexpr int SEQ   = 2048;
static constexpr int DIM   = 1024;

// Scratch (device globals: allocation-guard safe)
__device__ __half g_x  [BATCH * SEQ * DIM];        // fp16 x
__device__ __half g_w  [3 * DIM * DIM];            // concat Wq|Wk|Wv fp16
__device__ float  g_b  [3 * DIM];                  // concat bq|bk|bv fp32
__device__ __half g_qkv[BATCH * SEQ * 3 * DIM];    // fused Q|K|V rows
__device__ __half g_vt [BATCH * DIM * SEQ];        // V^T: [B][D][S]
__device__ __half g_p  [BATCH * SEQ * SEQ];        // fp16 attention weights

// ---------------------------------------------------------------------------
__device__ __forceinline__ void mma_f16(float (&c)[4],
                                        uint32_t a0, uint32_t a1,
                                        uint32_t a2, uint32_t a3,
                                        uint32_t b0, uint32_t b1) {
    asm volatile(
        "mma.sync.aligned.m16n8k16.row.col.f32.f16.f16.f32 "
        "{%0,%1,%2,%3}, {%4,%5,%6,%7}, {%8,%9}, {%0,%1,%2,%3};\n"
        : "+f"(c[0]), "+f"(c[1]), "+f"(c[2]), "+f"(c[3])
        : "r"(a0), "r"(a1), "r"(a2), "r"(a3), "r"(b0), "r"(b1));
}

__device__ __forceinline__ void ldsm4(uint32_t& r0, uint32_t& r1,
                                      uint32_t& r2, uint32_t& r3, uint32_t addr) {
    asm volatile(
        "ldmatrix.sync.aligned.m8n8.x4.shared.b16 {%0,%1,%2,%3}, [%4];"
        : "=r"(r0), "=r"(r1), "=r"(r2), "=r"(r3) : "r"(addr));
}

#define CPA16(dst, src) \
    asm volatile("cp.async.cg.shared.global [%0], [%1], 16;\n" :: "r"(dst), "l"(src))

// ---------------------------------------------------------------------------
// fp32 -> fp16 conversion passes
// ---------------------------------------------------------------------------
__global__ __launch_bounds__(256)
void cvt_half_kernel(const float* __restrict__ in, __half* __restrict__ out, int n4)
{
    int i = blockIdx.x * 256 + threadIdx.x;
    if (i < n4) {
        float4 v = ((const float4*)in)[i];
        __half2 h01 = __floats2half2_rn(v.x, v.y);
        __half2 h23 = __floats2half2_rn(v.z, v.w);
        uint2 pk;
        pk.x = *(uint32_t*)&h01;
        pk.y = *(uint32_t*)&h23;
        ((uint2*)out)[i] = pk;
    }
}

__global__ __launch_bounds__(256)
void cvt3_kernel(const float* __restrict__ w0, const float* __restrict__ w1,
                 const float* __restrict__ w2, __half* __restrict__ out, int nw4)
{
    int i = blockIdx.x * 256 + threadIdx.x;
    if (i < 3 * nw4) {
        const float* src = (i < nw4) ? w0 : (i < 2 * nw4 ? w1 : w2);
        int j = (i < nw4) ? i : (i < 2 * nw4 ? i - nw4 : i - 2 * nw4);
        float4 v = ((const float4*)src)[j];
        __half2 h01 = __floats2half2_rn(v.x, v.y);
        __half2 h23 = __floats2half2_rn(v.z, v.w);
        uint2 pk;
        pk.x = *(uint32_t*)&h01;
        pk.y = *(uint32_t*)&h23;
        ((uint2*)out)[i] = pk;
    }
}

__global__ __launch_bounds__(256)
void bias3_kernel(const float* __restrict__ b0, const float* __restrict__ b1,
                  const float* __restrict__ b2, float* __restrict__ out)
{
    int i = blockIdx.x * 256 + threadIdx.x;
    if (i < DIM)           out[i] = b0[i];
    else if (i < 2 * DIM)  out[i] = b1[i - DIM];
    else if (i < 3 * DIM)  out[i] = b2[i - 2 * DIM];
}

// ---------------------------------------------------------------------------
// FP16 tensor-core GEMM (fp32 accum):  C = alpha * (A @ B^T) + bias
//   A [M x K] lda, B [N x K] ldb, row-major fp16, explicit leading dims.
// 128x128 block tile. Pair-scheme: 2 sub-tiles of BK=32 per ONE
// __syncthreads; 3-pair ring (96 KB), ldmatrix fragment loads from
// XOR-swizzled 64B-row tiles, mma.m16n8k16, 256 threads (8 warps,
// 64x32 warp tiles), 2 CTAs/SM.
//   HALF_OUT: store C fp16 (operand reuse); else fp32.
//   VT_OUT:   additionally scatter cols >= 2*DIM (the V third of the fused
//             QKV output) transposed into vt[b][d][s]  (epilogue only).
// ---------------------------------------------------------------------------
template <bool HALF_OUT, bool VT_OUT>
__global__ __launch_bounds__(256, 2)
void gemm_h(const __half* __restrict__ A, const __half* __restrict__ B,
            const float* __restrict__ bias, void* __restrict__ C,
            __half* __restrict__ vt,
            int N, int K, int lda, int ldb, int ldc, float alpha,
            long sA, long sB, long sC)
{
    constexpr int SUB_H  = 128 * 32;           // halves per matrix sub-tile (8 KB)
    constexpr int PAIR_H = 4 * SUB_H;          // A0,B0,A1,B1 (32 KB)

    extern __shared__ __half smh[];
    uint32_t sbase;
    asm("{ .reg .u64 t; cvta.to.shared.u64 t, %1; cvt.u32.u64 %0, t; }"
        : "=r"(sbase) : "l"(smh));

    const __half* Ab = A + (long)blockIdx.z * sA;
    const __half* Bb = B + (long)blockIdx.z * sB;

    const int n0   = blockIdx.x * 128;
    const int m0   = blockIdx.y * 128;
    const int tid  = threadIdx.x;
    const int warp = tid >> 5;
    const int lane = tid & 31;
    const int g    = lane >> 2;
    const int tg   = lane & 3;
    const int wm   = (warp & 1) * 64;
    const int wn   = (warp >> 1) * 32;

    // Per-lane LDSM addressing
    const int lrow = ((lane >> 3) & 1) * 8 + (lane & 7);   // 0..15
    const uint32_t hi = lane >> 4;                          // 0/1

    uint32_t offA[4], swA[4];
    #pragma unroll
    for (int mi = 0; mi < 4; ++mi) {
        int r = wm + mi * 16 + lrow;
        offA[mi] = (uint32_t)r * 64u;
        swA[mi]  = ((uint32_t)r >> 1) & 3u;
    }
    uint32_t offB[2], swB[2];
    #pragma unroll
    for (int nj = 0; nj < 2; ++nj) {
        int r = wn + nj * 16 + lrow;
        offB[nj] = (uint32_t)r * 64u;
        swB[nj]  = ((uint32_t)r >> 1) & 3u;
    }

    float acc[4][4][4];
    #pragma unroll
    for (int i = 0; i < 4; ++i)
        #pragma unroll
        for (int j = 0; j < 4; ++j)
            #pragma unroll
            for (int r = 0; r < 4; ++r) acc[i][j][r] = 0.0f;

    // Pair loader: pair p covers k = [64p, 64p+64); ring slot = p % 3.
    auto load_pair = [&](int p) {
        const int s  = p % 3;
        const int cr = tid >> 1;
        const int cp = (tid & 1) * 2;
        const uint32_t sw = ((uint32_t)cr >> 1) & 3u;
        #pragma unroll
        for (int sub = 0; sub < 2; ++sub) {
            const int k0 = p * 64 + sub * 32;
            const uint32_t abase = sbase + (uint32_t)(s * PAIR_H + sub * 2 * SUB_H) * 2u
                                         + (uint32_t)cr * 64u;
            const uint32_t bbase = abase + (uint32_t)SUB_H * 2u;
            const __half* asrc = Ab + (long)(m0 + cr) * lda + k0 + cp * 8;
            const __half* bsrc = Bb + (long)(n0 + cr) * ldb + k0 + cp * 8;
            CPA16(abase + ((((uint32_t)cp    ) ^ sw) << 4), asrc);
            CPA16(abase + ((((uint32_t)cp + 1) ^ sw) << 4), asrc + 8);
            CPA16(bbase + ((((uint32_t)cp    ) ^ sw) << 4), bsrc);
            CPA16(bbase + ((((uint32_t)cp + 1) ^ sw) << 4), bsrc + 8);
        }
        asm volatile("cp.async.commit_group;\n");
    };

    const int npairs = K / 64;
    load_pair(0);
    load_pair(1);

    for (int p = 0; p < npairs; ++p) {
        if (p + 1 < npairs) asm volatile("cp.async.wait_group 1;\n");
        else                asm volatile("cp.async.wait_group 0;\n");
        __syncthreads();
        // Slots for pair p+2 are (p+2)%3 == (p-1)%3: computed in iteration
        // p-1; the barrier above guarantees all warps finished that compute.
        if (p + 2 < npairs) load_pair(p + 2);

        const uint32_t pbase = sbase + (uint32_t)((p % 3) * PAIR_H) * 2u;

        #pragma unroll
        for (int sub = 0; sub < 2; ++sub) {
            const uint32_t Ab32 = pbase + (uint32_t)(sub * 2 * SUB_H) * 2u;
            const uint32_t Bb32 = Ab32 + (uint32_t)SUB_H * 2u;
            #pragma unroll
            for (int kk = 0; kk < 2; ++kk) {
                const uint32_t c0 = (uint32_t)(kk * 2) + hi;
                uint32_t af[4][4], bf[2][4];
                #pragma unroll
                for (int mi = 0; mi < 4; ++mi)
                    ldsm4(af[mi][0], af[mi][1], af[mi][2], af[mi][3],
                          Ab32 + offA[mi] + ((c0 ^ swA[mi]) << 4));
                #pragma unroll
                for (int nj = 0; nj < 2; ++nj)
                    ldsm4(bf[nj][0], bf[nj][1], bf[nj][2], bf[nj][3],
                          Bb32 + offB[nj] + ((c0 ^ swB[nj]) << 4));
                #pragma unroll
                for (int mi = 0; mi < 4; ++mi)
                    #pragma unroll
                    for (int ni = 0; ni < 4; ++ni) {
                        const int nj = ni >> 1, lo = ni & 1;
                        mma_f16(acc[mi][ni], af[mi][0], af[mi][1], af[mi][2],
                                af[mi][3], bf[nj][lo], bf[nj][2 + lo]);
                    }
            }
        }
    }

    // Epilogue
    #pragma unroll
    for (int mi = 0; mi < 4; ++mi) {
        const int row = m0 + wm + mi * 16 + g;
        #pragma unroll
        for (int ni = 0; ni < 4; ++ni) {
            const int col = n0 + wn + ni * 8 + tg * 2;
            float v0 = acc[mi][ni][0] * alpha, v1 = acc[mi][ni][1] * alpha;
            float v2 = acc[mi][ni][2] * alpha, v3 = acc[mi][ni][3] * alpha;
            if (bias) {
                float2 b = *(const float2*)&bias[col];
                v0 += b.x; v1 += b.y; v2 += b.x; v3 += b.y;
            }
            if (HALF_OUT) {
                __half* Cb = (__half*)C + (long)blockIdx.z * sC;
                __half2 h0 = __floats2half2_rn(v0, v1);
                __half2 h1 = __floats2half2_rn(v2, v3);
                *(__half2*)&Cb[(long)row * ldc + col]       = h0;
                *(__half2*)&Cb[(long)(row + 8) * ldc + col] = h1;
                if (VT_OUT && col >= 2 * DIM) {
                    // fused V^T: vt[b][d][s], b = row/SEQ, s = row%SEQ
                    const int d  = col - 2 * DIM;
                    const int b0i = row >> 11;          // SEQ = 2048
                    const int s0i = row & (SEQ - 1);
                    __half* vtb = vt + (long)b0i * DIM * SEQ;
                    vtb[(long)(d)     * SEQ + s0i]     = __low2half(h0);
                    vtb[(long)(d + 1) * SEQ + s0i]     = __high2half(h0);
                    vtb[(long)(d)     * SEQ + s0i + 8] = __low2half(h1);
                    vtb[(long)(d + 1) * SEQ + s0i + 8] = __high2half(h1);
                }
            } else {
                float* Cb = (float*)C + (long)blockIdx.z * sC;
                *(float2*)&Cb[(long)row * ldc + col]       = make_float2(v0, v1);
                *(float2*)&Cb[(long)(row + 8) * ldc + col] = make_float2(v2, v3);
            }
        }
    }
}

// ---------------------------------------------------------------------------
// Row softmax, float4-vectorized: thread t owns elements [8t, 8t+8).
// Exact fp32 -> data (in place); fp16 copy -> ph.
// ---------------------------------------------------------------------------
__global__ __launch_bounds__(256)
void softmax_kernel(float* __restrict__ data, __half* __restrict__ ph)
{
    const long roff = (long)blockIdx.x * SEQ;
    float4* r4 = (float4*)(data + roff);
    uint4*  h4 = (uint4*)(ph + roff);
    __shared__ float red[8];

    const int tid  = threadIdx.x;
    const int lane = tid & 31;
    const int warp = tid >> 5;

    float4 va = r4[2 * tid];
    float4 vb = r4[2 * tid + 1];

    float lmax = fmaxf(fmaxf(fmaxf(va.x, va.y), fmaxf(va.z, va.w)),
                       fmaxf(fmaxf(vb.x, vb.y), fmaxf(vb.z, vb.w)));
    #pragma unroll
    for (int o = 16; o > 0; o >>= 1)
        lmax = fmaxf(lmax, __shfl_xor_sync(0xFFFFFFFFu, lmax, o));
    if (lane == 0) red[warp] = lmax;
    __syncthreads();
    float rmax = red[0];
    #pragma unroll
    for (int w = 1; w < 8; ++w) rmax = fmaxf(rmax, red[w]);
    __syncthreads();

    va.x = __expf(va.x - rmax); va.y = __expf(va.y - rmax);
    va.z = __expf(va.z - rmax); va.w = __expf(va.w - rmax);
    vb.x = __expf(vb.x - rmax); vb.y = __expf(vb.y - rmax);
    vb.z = __expf(vb.z - rmax); vb.w = __expf(vb.w - rmax);

    float lsum = (va.x + va.y) + (va.z + va.w) + (vb.x + vb.y) + (vb.z + vb.w);
    #pragma unroll
    for (int o = 16; o > 0; o >>= 1)
        lsum += __shfl_xor_sync(0xFFFFFFFFu, lsum, o);
    if (lane == 0) red[warp] = lsum;
    __syncthreads();
    float rsum = 0.0f;
    #pragma unroll
    for (int w = 0; w < 8; ++w) rsum += red[w];

    const float inv = 1.0f / rsum;
    va.x *= inv; va.y *= inv; va.z *= inv; va.w *= inv;
    vb.x *= inv; vb.y *= inv; vb.z *= inv; vb.w *= inv;

    r4[2 * tid]     = va;
    r4[2 * tid + 1] = vb;

    __half2 p0 = __floats2half2_rn(va.x, va.y);
    __half2 p1 = __floats2half2_rn(va.z, va.w);
    __half2 p2 = __floats2half2_rn(vb.x, vb.y);
    __half2 p3 = __floats2half2_rn(vb.z, vb.w);
    uint4 pk;
    pk.x = *(uint32_t*)&p0; pk.y = *(uint32_t*)&p1;
    pk.z = *(uint32_t*)&p2; pk.w = *(uint32_t*)&p3;
    h4[tid] = pk;
}

// ---------------------------------------------------------------------------
// Launch: cvt -> fused QKV proj (+fused V^T) -> scores -> softmax -> AV
// Output layout: [weighted_sum B*S*D | attention_weights B*S*S]
// ---------------------------------------------------------------------------
extern "C" void kernel_launch(void* const* d_in, const int* in_sizes, int n_in,
                              void* d_out, int out_size)
{
    const float* x  = (const float*)d_in[0];
    const float* Wq = (const float*)d_in[1];
    const float* bq = (const float*)d_in[2];
    const float* Wk = (const float*)d_in[3];
    const float* bk = (const float*)d_in[4];
    const float* Wv = (const float*)d_in[5];
    const float* bv = (const float*)d_in[6];

    float* out_ws = (float*)d_out;
    float* out_aw = (float*)d_out + (long)BATCH * SEQ * DIM;

    __half *xh, *w, *qkv, *vt, *p;
    float* b;
    cudaGetSymbolAddress((void**)&xh,  g_x);
    cudaGetSymbolAddress((void**)&w,   g_w);
    cudaGetSymbolAddress((void**)&b,   g_b);
    cudaGetSymbolAddress((void**)&qkv, g_qkv);
    cudaGetSymbolAddress((void**)&vt,  g_vt);
    cudaGetSymbolAddress((void**)&p,   g_p);

    // smem: 3 pairs x 32768 B = 98304 B per CTA (2 CTAs/SM = 192 KB)
    const int smem_sz = 3 * 4 * 128 * 32 * 2;
    cudaFuncSetAttribute(gemm_h<true,  true >, cudaFuncAttributeMaxDynamicSharedMemorySize, smem_sz);
    cudaFuncSetAttribute(gemm_h<false, false>, cudaFuncAttributeMaxDynamicSharedMemorySize, smem_sz);

    const dim3 blk(256);

    // 0) convert inputs to fp16 (x; Wq|Wk|Wv concat; bias concat)
    {
        const int nx = BATCH * SEQ * DIM / 4;
        const int nw = DIM * DIM / 4;
        cvt_half_kernel<<<(nx + 255) / 256, blk>>>(x, xh, nx);
        cvt3_kernel<<<(3 * nw + 255) / 256, blk>>>(Wq, Wk, Wv, w, nw);
        bias3_kernel<<<(3 * DIM + 255) / 256, blk>>>(bq, bk, bv, b);
    }

    // 1) Fused QKV projection: [8192, 3072] = xh @ W^T + b, fp16 out.
    //    V third additionally scattered transposed into vt[b][d][s].
    {
        dim3 grid((3 * DIM) / 128, (BATCH * SEQ) / 128, 1);
        gemm_h<true, true><<<grid, blk, smem_sz>>>(xh, w, b, qkv, vt,
                                                   3 * DIM, DIM,
                                                   DIM, DIM, 3 * DIM, 1.0f,
                                                   0, 0, 0);
    }

    // 2) scores = (Q @ K^T) / 32, fp32 into attention-weights region
    {
        dim3 grid(SEQ / 128, SEQ / 128, BATCH);
        gemm_h<false, false><<<grid, blk, smem_sz>>>(qkv, qkv + DIM, nullptr,
                                                     out_aw, nullptr,
                                                     SEQ, DIM,
                                                     3 * DIM, 3 * DIM, SEQ, 0.03125f,
                                                     (long)SEQ * 3 * DIM,
                                                     (long)SEQ * 3 * DIM,
                                                     (long)SEQ * SEQ);
    }

    // 3) softmax: exact fp32 -> out_aw, fp16 -> p
    softmax_kernel<<<BATCH * SEQ, blk>>>(out_aw, p);

    // 4) weighted_sum = P @ Vt^T  (Vt: [D,S] = B[N=D,K=S]), fp32 out
    {
        dim3 grid(DIM / 128, SEQ / 128, BATCH);
        gemm_h<false, false><<<grid, blk, smem_sz>>>(p, vt, nullptr,
                                                     out_ws, nullptr,
                                                     DIM, SEQ,
                                                     SEQ, SEQ, DIM, 1.0f,
                                                     (long)SEQ * SEQ,
                                                     (long)DIM * SEQ,
                                                     (long)SEQ * DIM);
    }
}

// round 17
// speedup vs baseline: 1.4179x; 1.0737x over previous
#include <cuda_runtime.h>
#include <cuda_fp16.h>
#include <cstdint>

static constexpr int BATCH = 4;
static constexpr int SEQ   = 2048;
static constexpr int DIM   = 1024;

// Scratch (device globals: allocation-guard safe)
__device__ __half g_x  [BATCH * SEQ * DIM];        // fp16 x
__device__ __half g_w  [3 * DIM * DIM];            // concat Wq|Wk|Wv fp16
__device__ float  g_b  [3 * DIM];                  // concat bq|bk|bv fp32
__device__ __half g_qkv[BATCH * SEQ * 3 * DIM];    // fused Q|K|V rows
__device__ __half g_vt [BATCH * DIM * SEQ];        // V^T: [B][D][S]
__device__ __half g_p  [BATCH * SEQ * SEQ];        // fp16 attention weights

// ---------------------------------------------------------------------------
__device__ __forceinline__ void mma_f16(float (&c)[4],
                                        uint32_t a0, uint32_t a1,
                                        uint32_t a2, uint32_t a3,
                                        uint32_t b0, uint32_t b1) {
    asm volatile(
        "mma.sync.aligned.m16n8k16.row.col.f32.f16.f16.f32 "
        "{%0,%1,%2,%3}, {%4,%5,%6,%7}, {%8,%9}, {%0,%1,%2,%3};\n"
        : "+f"(c[0]), "+f"(c[1]), "+f"(c[2]), "+f"(c[3])
        : "r"(a0), "r"(a1), "r"(a2), "r"(a3), "r"(b0), "r"(b1));
}

__device__ __forceinline__ void ldsm4(uint32_t& r0, uint32_t& r1,
                                      uint32_t& r2, uint32_t& r3, uint32_t addr) {
    asm volatile(
        "ldmatrix.sync.aligned.m8n8.x4.shared.b16 {%0,%1,%2,%3}, [%4];"
        : "=r"(r0), "=r"(r1), "=r"(r2), "=r"(r3) : "r"(addr));
}

#define CPA16(dst, src) \
    asm volatile("cp.async.cg.shared.global [%0], [%1], 16;\n" :: "r"(dst), "l"(src))

// ---------------------------------------------------------------------------
// fp32 -> fp16 conversion passes
// ---------------------------------------------------------------------------
__global__ __launch_bounds__(256)
void cvt_half_kernel(const float* __restrict__ in, __half* __restrict__ out, int n4)
{
    int i = blockIdx.x * 256 + threadIdx.x;
    if (i < n4) {
        float4 v = ((const float4*)in)[i];
        __half2 h01 = __floats2half2_rn(v.x, v.y);
        __half2 h23 = __floats2half2_rn(v.z, v.w);
        uint2 pk;
        pk.x = *(uint32_t*)&h01;
        pk.y = *(uint32_t*)&h23;
        ((uint2*)out)[i] = pk;
    }
}

__global__ __launch_bounds__(256)
void cvt3_kernel(const float* __restrict__ w0, const float* __restrict__ w1,
                 const float* __restrict__ w2, __half* __restrict__ out, int nw4)
{
    int i = blockIdx.x * 256 + threadIdx.x;
    if (i < 3 * nw4) {
        const float* src = (i < nw4) ? w0 : (i < 2 * nw4 ? w1 : w2);
        int j = (i < nw4) ? i : (i < 2 * nw4 ? i - nw4 : i - 2 * nw4);
        float4 v = ((const float4*)src)[j];
        __half2 h01 = __floats2half2_rn(v.x, v.y);
        __half2 h23 = __floats2half2_rn(v.z, v.w);
        uint2 pk;
        pk.x = *(uint32_t*)&h01;
        pk.y = *(uint32_t*)&h23;
        ((uint2*)out)[i] = pk;
    }
}

__global__ __launch_bounds__(256)
void bias3_kernel(const float* __restrict__ b0, const float* __restrict__ b1,
                  const float* __restrict__ b2, float* __restrict__ out)
{
    int i = blockIdx.x * 256 + threadIdx.x;
    if (i < DIM)           out[i] = b0[i];
    else if (i < 2 * DIM)  out[i] = b1[i - DIM];
    else if (i < 3 * DIM)  out[i] = b2[i - 2 * DIM];
}

// ---------------------------------------------------------------------------
// FP16 tensor-core GEMM (fp32 accum):  C = alpha * (A @ B^T) + bias
//   A [M x K] lda, B [N x K] ldb, row-major fp16, explicit leading dims.
// 128x64 block tile, BK=32, 256 threads (8 warps, 32x32 warp tiles),
// 3-stage cp.async ring with ONE __syncthreads per K-tile, ldmatrix
// fragment loads from XOR-swizzled 64B-row tiles, mma.m16n8k16,
// 3 CTAs/SM (24 warps/SM: 6 warps/SMSP for latency hiding).
//   HALF_OUT: store C fp16 (operand reuse); else fp32.
//   VT_OUT:   additionally scatter cols >= 2*DIM transposed into vt[b][d][s].
// ---------------------------------------------------------------------------
template <bool HALF_OUT, bool VT_OUT>
__global__ __launch_bounds__(256, 3)
void gemm_h(const __half* __restrict__ A, const __half* __restrict__ B,
            const float* __restrict__ bias, void* __restrict__ C,
            __half* __restrict__ vt,
            int N, int K, int lda, int ldb, int ldc, float alpha,
            long sA, long sB, long sC)
{
    constexpr int BK  = 32;
    constexpr int A_H   = 128 * 32;            // A tile halves (8 KB)
    constexpr int B_H   = 64  * 32;            // B tile halves (4 KB)
    constexpr int STG_H = A_H + B_H;           // stage halves (12 KB)

    extern __shared__ __half smh[];
    uint32_t sbase;
    asm("{ .reg .u64 t; cvta.to.shared.u64 t, %1; cvt.u32.u64 %0, t; }"
        : "=r"(sbase) : "l"(smh));

    const __half* Ab = A + (long)blockIdx.z * sA;
    const __half* Bb = B + (long)blockIdx.z * sB;

    const int n0   = blockIdx.x * 64;
    const int m0   = blockIdx.y * 128;
    const int tid  = threadIdx.x;
    const int warp = tid >> 5;
    const int lane = tid & 31;
    const int g    = lane >> 2;
    const int tg   = lane & 3;
    const int wm   = (warp & 3) * 32;          // 4 warps across M
    const int wn   = (warp >> 2) * 32;         // 2 warps across N

    // Per-lane LDSM addressing
    const int lrow = ((lane >> 3) & 1) * 8 + (lane & 7);   // 0..15
    const uint32_t hi = lane >> 4;                          // 0/1

    uint32_t offA[2], swA[2];
    #pragma unroll
    for (int mi = 0; mi < 2; ++mi) {
        int r = wm + mi * 16 + lrow;
        offA[mi] = (uint32_t)r * 64u;
        swA[mi]  = ((uint32_t)r >> 1) & 3u;
    }
    uint32_t offB[2], swB[2];
    #pragma unroll
    for (int nj = 0; nj < 2; ++nj) {
        int r = wn + nj * 16 + lrow;
        offB[nj] = (uint32_t)r * 64u;
        swB[nj]  = ((uint32_t)r >> 1) & 3u;
    }

    float acc[2][4][4];
    #pragma unroll
    for (int i = 0; i < 2; ++i)
        #pragma unroll
        for (int j = 0; j < 4; ++j)
            #pragma unroll
            for (int r = 0; r < 4; ++r) acc[i][j][r] = 0.0f;

    // Loader (256 threads): A 128 rows x 2 thr/row x 2 chunks;
    //                       B 64 rows x 4 thr/row x 1 chunk.
    auto load_tile = [&](int kt, int s) {
        const int k0 = kt * BK;
        {
            const int cr = tid >> 1;           // 0..127
            const int cp = (tid & 1) * 2;
            const uint32_t sw = ((uint32_t)cr >> 1) & 3u;
            const uint32_t abase = sbase + (uint32_t)(s * STG_H) * 2u
                                         + (uint32_t)cr * 64u;
            const __half* asrc = Ab + (long)(m0 + cr) * lda + k0 + cp * 8;
            CPA16(abase + ((((uint32_t)cp    ) ^ sw) << 4), asrc);
            CPA16(abase + ((((uint32_t)cp + 1) ^ sw) << 4), asrc + 8);
        }
        {
            const int cr = tid >> 2;           // 0..63
            const int cp = tid & 3;            // chunk 0..3
            const uint32_t sw = ((uint32_t)cr >> 1) & 3u;
            const uint32_t bbase = sbase + (uint32_t)(s * STG_H + A_H) * 2u
                                         + (uint32_t)cr * 64u;
            CPA16(bbase + ((((uint32_t)cp) ^ sw) << 4),
                  Bb + (long)(n0 + cr) * ldb + k0 + cp * 8);
        }
        asm volatile("cp.async.commit_group;\n");
    };

    const int ntiles = K / BK;
    load_tile(0, 0);
    load_tile(1, 1);

    for (int kt = 0; kt < ntiles; ++kt) {
        const int s = kt % 3;
        if (kt + 1 < ntiles) asm volatile("cp.async.wait_group 1;\n");
        else                 asm volatile("cp.async.wait_group 0;\n");
        __syncthreads();
        // Stage (kt+2)%3 was last read in iteration kt-1; the barrier above
        // guarantees all warps finished that compute.
        if (kt + 2 < ntiles) load_tile(kt + 2, (kt + 2) % 3);

        const uint32_t Ab32 = sbase + (uint32_t)(s * STG_H) * 2u;
        const uint32_t Bb32 = Ab32 + (uint32_t)A_H * 2u;

        #pragma unroll
        for (int kk = 0; kk < 2; ++kk) {       // 2 x K=16 per BK=32
            const uint32_t c0 = (uint32_t)(kk * 2) + hi;
            uint32_t af[2][4], bf[2][4];
            #pragma unroll
            for (int mi = 0; mi < 2; ++mi)
                ldsm4(af[mi][0], af[mi][1], af[mi][2], af[mi][3],
                      Ab32 + offA[mi] + ((c0 ^ swA[mi]) << 4));
            #pragma unroll
            for (int nj = 0; nj < 2; ++nj)
                ldsm4(bf[nj][0], bf[nj][1], bf[nj][2], bf[nj][3],
                      Bb32 + offB[nj] + ((c0 ^ swB[nj]) << 4));
            #pragma unroll
            for (int mi = 0; mi < 2; ++mi)
                #pragma unroll
                for (int ni = 0; ni < 4; ++ni) {
                    const int nj = ni >> 1, lo = ni & 1;
                    mma_f16(acc[mi][ni], af[mi][0], af[mi][1], af[mi][2],
                            af[mi][3], bf[nj][lo], bf[nj][2 + lo]);
                }
        }
    }

    // Epilogue
    #pragma unroll
    for (int mi = 0; mi < 2; ++mi) {
        const int row = m0 + wm + mi * 16 + g;
        #pragma unroll
        for (int ni = 0; ni < 4; ++ni) {
            const int col = n0 + wn + ni * 8 + tg * 2;
            float v0 = acc[mi][ni][0] * alpha, v1 = acc[mi][ni][1] * alpha;
            float v2 = acc[mi][ni][2] * alpha, v3 = acc[mi][ni][3] * alpha;
            if (bias) {
                float2 b = *(const float2*)&bias[col];
                v0 += b.x; v1 += b.y; v2 += b.x; v3 += b.y;
            }
            if (HALF_OUT) {
                __half* Cb = (__half*)C + (long)blockIdx.z * sC;
                __half2 h0 = __floats2half2_rn(v0, v1);
                __half2 h1 = __floats2half2_rn(v2, v3);
                *(__half2*)&Cb[(long)row * ldc + col]       = h0;
                *(__half2*)&Cb[(long)(row + 8) * ldc + col] = h1;
                if (VT_OUT && col >= 2 * DIM) {
                    // fused V^T: vt[b][d][s], b = row/SEQ, s = row%SEQ
                    const int d   = col - 2 * DIM;
                    const int b0i = row >> 11;          // SEQ = 2048
                    const int s0i = row & (SEQ - 1);
                    __half* vtb = vt + (long)b0i * DIM * SEQ;
                    vtb[(long)(d)     * SEQ + s0i]     = __low2half(h0);
                    vtb[(long)(d + 1) * SEQ + s0i]     = __high2half(h0);
                    vtb[(long)(d)     * SEQ + s0i + 8] = __low2half(h1);
                    vtb[(long)(d + 1) * SEQ + s0i + 8] = __high2half(h1);
                }
            } else {
                float* Cb = (float*)C + (long)blockIdx.z * sC;
                *(float2*)&Cb[(long)row * ldc + col]       = make_float2(v0, v1);
                *(float2*)&Cb[(long)(row + 8) * ldc + col] = make_float2(v2, v3);
            }
        }
    }
}

// ---------------------------------------------------------------------------
// Row softmax, float4-vectorized: thread t owns elements [8t, 8t+8).
// Exact fp32 -> data (in place); fp16 copy -> ph.
// ---------------------------------------------------------------------------
__global__ __launch_bounds__(256)
void softmax_kernel(float* __restrict__ data, __half* __restrict__ ph)
{
    const long roff = (long)blockIdx.x * SEQ;
    float4* r4 = (float4*)(data + roff);
    uint4*  h4 = (uint4*)(ph + roff);
    __shared__ float red[8];

    const int tid  = threadIdx.x;
    const int lane = tid & 31;
    const int warp = tid >> 5;

    float4 va = r4[2 * tid];
    float4 vb = r4[2 * tid + 1];

    float lmax = fmaxf(fmaxf(fmaxf(va.x, va.y), fmaxf(va.z, va.w)),
                       fmaxf(fmaxf(vb.x, vb.y), fmaxf(vb.z, vb.w)));
    #pragma unroll
    for (int o = 16; o > 0; o >>= 1)
        lmax = fmaxf(lmax, __shfl_xor_sync(0xFFFFFFFFu, lmax, o));
    if (lane == 0) red[warp] = lmax;
    __syncthreads();
    float rmax = red[0];
    #pragma unroll
    for (int w = 1; w < 8; ++w) rmax = fmaxf(rmax, red[w]);
    __syncthreads();

    va.x = __expf(va.x - rmax); va.y = __expf(va.y - rmax);
    va.z = __expf(va.z - rmax); va.w = __expf(va.w - rmax);
    vb.x = __expf(vb.x - rmax); vb.y = __expf(vb.y - rmax);
    vb.z = __expf(vb.z - rmax); vb.w = __expf(vb.w - rmax);

    float lsum = (va.x + va.y) + (va.z + va.w) + (vb.x + vb.y) + (vb.z + vb.w);
    #pragma unroll
    for (int o = 16; o > 0; o >>= 1)
        lsum += __shfl_xor_sync(0xFFFFFFFFu, lsum, o);
    if (lane == 0) red[warp] = lsum;
    __syncthreads();
    float rsum = 0.0f;
    #pragma unroll
    for (int w = 0; w < 8; ++w) rsum += red[w];

    const float inv = 1.0f / rsum;
    va.x *= inv; va.y *= inv; va.z *= inv; va.w *= inv;
    vb.x *= inv; vb.y *= inv; vb.z *= inv; vb.w *= inv;

    r4[2 * tid]     = va;
    r4[2 * tid + 1] = vb;

    __half2 p0 = __floats2half2_rn(va.x, va.y);
    __half2 p1 = __floats2half2_rn(va.z, va.w);
    __half2 p2 = __floats2half2_rn(vb.x, vb.y);
    __half2 p3 = __floats2half2_rn(vb.z, vb.w);
    uint4 pk;
    pk.x = *(uint32_t*)&p0; pk.y = *(uint32_t*)&p1;
    pk.z = *(uint32_t*)&p2; pk.w = *(uint32_t*)&p3;
    h4[tid] = pk;
}

// ---------------------------------------------------------------------------
// Launch: cvt -> fused QKV proj (+fused V^T) -> scores -> softmax -> AV
// Output layout: [weighted_sum B*S*D | attention_weights B*S*S]
// ---------------------------------------------------------------------------
extern "C" void kernel_launch(void* const* d_in, const int* in_sizes, int n_in,
                              void* d_out, int out_size)
{
    const float* x  = (const float*)d_in[0];
    const float* Wq = (const float*)d_in[1];
    const float* bq = (const float*)d_in[2];
    const float* Wk = (const float*)d_in[3];
    const float* bk = (const float*)d_in[4];
    const float* Wv = (const float*)d_in[5];
    const float* bv = (const float*)d_in[6];

    float* out_ws = (float*)d_out;
    float* out_aw = (float*)d_out + (long)BATCH * SEQ * DIM;

    __half *xh, *w, *qkv, *vt, *p;
    float* b;
    cudaGetSymbolAddress((void**)&xh,  g_x);
    cudaGetSymbolAddress((void**)&w,   g_w);
    cudaGetSymbolAddress((void**)&b,   g_b);
    cudaGetSymbolAddress((void**)&qkv, g_qkv);
    cudaGetSymbolAddress((void**)&vt,  g_vt);
    cudaGetSymbolAddress((void**)&p,   g_p);

    // smem: 3 stages x 12288 B = 36864 B per CTA (3 CTAs/SM = 110 KB)
    const int smem_sz = 3 * (128 * 32 + 64 * 32) * 2;
    cudaFuncSetAttribute(gemm_h<true,  true >, cudaFuncAttributeMaxDynamicSharedMemorySize, smem_sz);
    cudaFuncSetAttribute(gemm_h<false, false>, cudaFuncAttributeMaxDynamicSharedMemorySize, smem_sz);

    const dim3 blk(256);

    // 0) convert inputs to fp16 (x; Wq|Wk|Wv concat; bias concat)
    {
        const int nx = BATCH * SEQ * DIM / 4;
        const int nw = DIM * DIM / 4;
        cvt_half_kernel<<<(nx + 255) / 256, blk>>>(x, xh, nx);
        cvt3_kernel<<<(3 * nw + 255) / 256, blk>>>(Wq, Wk, Wv, w, nw);
        bias3_kernel<<<(3 * DIM + 255) / 256, blk>>>(bq, bk, bv, b);
    }

    // 1) Fused QKV projection: [8192, 3072] = xh @ W^T + b, fp16 out.
    //    V third additionally scattered transposed into vt[b][d][s].
    {
        dim3 grid((3 * DIM) / 64, (BATCH * SEQ) / 128, 1);
        gemm_h<true, true><<<grid, blk, smem_sz>>>(xh, w, b, qkv, vt,
                                                   3 * DIM, DIM,
                                                   DIM, DIM, 3 * DIM, 1.0f,
                                                   0, 0, 0);
    }

    // 2) scores = (Q @ K^T) / 32, fp32 into attention-weights region
    {
        dim3 grid(SEQ / 64, SEQ / 128, BATCH);
        gemm_h<false, false><<<grid, blk, smem_sz>>>(qkv, qkv + DIM, nullptr,
                                                     out_aw, nullptr,
                                                     SEQ, DIM,
                                                     3 * DIM, 3 * DIM, SEQ, 0.03125f,
                                                     (long)SEQ * 3 * DIM,
                                                     (long)SEQ * 3 * DIM,
                                                     (long)SEQ * SEQ);
    }

    // 3) softmax: exact fp32 -> out_aw, fp16 -> p
    softmax_kernel<<<BATCH * SEQ, blk>>>(out_aw, p);

    // 4) weighted_sum = P @ Vt^T  (Vt: [D,S] = B[N=D,K=S]), fp32 out
    {
        dim3 grid(DIM / 64, SEQ / 128, BATCH);
        gemm_h<false, false><<<grid, blk, smem_sz>>>(p, vt, nullptr,
                                                     out_ws, nullptr,
                                                     DIM, SEQ,
                                                     SEQ, SEQ, DIM, 1.0f,
                                                     (long)SEQ * SEQ,
                                                     (long)DIM * SEQ,
                                                     (long)SEQ * DIM);
    }
}